// round 9
// baseline (speedup 1.0000x reference)
#include <cuda_runtime.h>
#include <cuda_bf16.h>
#include <cstdint>

// ---------------- problem constants ----------------
#define NGn   32768
#define EGn   131072
#define ELGn  262144
#define Hn    128
#define NDn   32
#define EDn   16
#define NBn   4
#define Ln    4
#define Bn    256
#define TKn   10
#define EPSM  1e-7f
#define BNINV 0.9999950000374997f   // 1/sqrt(1+1e-5)

// ---------------- device scratch (no allocs allowed) ----------------
static __device__ float g_h[EGn * Hn];      // current line-graph node features (64 MiB)
static __device__ float g_y[EGn * Hn];      // u1,u2 during prep (64 MiB)
static __device__ float g_m[ELGn * Hn];     // per-CSR-slot messages (128 MiB)
static __device__ float g_P1[NDn * Hn];
static __device__ float g_P2[NDn * Hn];
static __device__ float g_beff[Hn];
static __device__ int   g_deg[EGn];
static __device__ int   g_off[EGn + 1];
static __device__ int   g_cur[EGn];
static __device__ int   g_bsum[128];
static __device__ int   g_bofs[128];
static __device__ int   g_csr_src[ELGn];
static __device__ int   g_csr_eid[ELGn];
static __device__ float g_nemb[NGn * Hn];   // 16 MiB
static __device__ __nv_bfloat16 g_WtH[Ln * Hn * Hn];  // W transposed, bf16 hi
static __device__ __nv_bfloat16 g_WtL[Ln * Hn * Hn];  // W transposed, bf16 lo
// node CSR (dst_g -> edge ids)
static __device__ int   g_ndeg[NGn];
static __device__ int   g_noff[NGn + 1];
static __device__ int   g_ncur[NGn];
static __device__ int   g_ncsr[EGn];
static __device__ int   g_nbsum[32];
static __device__ int   g_nbofs[32];

// ---------------- small vector helpers ----------------
__device__ __forceinline__ float4 f4zero() { return make_float4(0.f, 0.f, 0.f, 0.f); }
__device__ __forceinline__ float4 operator+(float4 a, float4 b) {
    return make_float4(a.x + b.x, a.y + b.y, a.z + b.z, a.w + b.w);
}
__device__ __forceinline__ void operator+=(float4& a, float4 b) {
    a.x += b.x; a.y += b.y; a.z += b.z; a.w += b.w;
}
__device__ __forceinline__ float4 operator*(float a, float4 b) {
    return make_float4(a * b.x, a * b.y, a * b.z, a * b.w);
}

// ---------------- portable tensor-core helpers ----------------
__device__ __forceinline__ uint32_t smem_u32(const void* p) {
    uint32_t a;
    asm("{ .reg .u64 t; cvta.to.shared.u64 t, %1; cvt.u32.u64 %0, t; }" : "=r"(a) : "l"(p));
    return a;
}
__device__ __forceinline__ void ldsm_x4(uint32_t* r, uint32_t addr) {
    asm volatile("ldmatrix.sync.aligned.m8n8.x4.shared.b16 {%0,%1,%2,%3}, [%4];"
                 : "=r"(r[0]), "=r"(r[1]), "=r"(r[2]), "=r"(r[3]) : "r"(addr));
}
__device__ __forceinline__ void mma_bf16(float* d, const uint32_t* a, const uint32_t* b) {
    asm volatile("mma.sync.aligned.m16n8k16.row.col.f32.bf16.bf16.f32 "
                 "{%0,%1,%2,%3}, {%4,%5,%6,%7}, {%8,%9}, {%0,%1,%2,%3};"
                 : "+f"(d[0]), "+f"(d[1]), "+f"(d[2]), "+f"(d[3])
                 : "r"(a[0]), "r"(a[1]), "r"(a[2]), "r"(a[3]), "r"(b[0]), "r"(b[1]));
}

// ---------------- param prep ----------------
__global__ void k_params(const float* __restrict__ W_enc, const float* __restrict__ W_msg,
                         const float* __restrict__ b_enc, const float* __restrict__ b_msg) {
    int f = threadIdx.x;
    int b = blockIdx.x;
    if (b < 32) {
        float acc = 0.f;
        for (int k = 0; k < Hn; k++) acc += W_enc[b * Hn + k] * W_msg[k * Hn + f];
        g_P1[b * Hn + f] = acc;
    } else if (b < 64) {
        int j = b - 32;
        float acc = 0.f;
        for (int k = 0; k < Hn; k++) acc += W_enc[j * Hn + k] * W_msg[(Hn + k) * Hn + f];
        g_P2[j * Hn + f] = acc;
    } else {
        float acc = b_msg[f];
        for (int k = 0; k < Hn; k++)
            acc += b_enc[k] * (W_msg[k * Hn + f] + W_msg[(Hn + k) * Hn + f]);
        g_beff[f] = acc;
    }
}

// ---------------- W transpose + bf16 hi/lo split ----------------
__global__ void k_wt(const float* __restrict__ W_gcn) {
    int i = blockIdx.x * blockDim.x + threadIdx.x;
    int l = i >> 14;
    int rem = i & 16383;
    int n = rem >> 7, k = rem & 127;
    float w = W_gcn[l * Hn * Hn + k * Hn + n];
    __nv_bfloat16 h = __float2bfloat16_rn(w);
    float r = w - __bfloat162float(h);
    g_WtH[i] = h;
    g_WtL[i] = __float2bfloat16_rn(r);
}

// ---------------- per-node u1/u2 ----------------
__global__ __launch_bounds__(128) void k_u(const float* __restrict__ x_g) {
    int f = threadIdx.x;
    float p1[NDn], p2[NDn];
#pragma unroll
    for (int j = 0; j < NDn; j++) {
        p1[j] = g_P1[j * Hn + f];
        p2[j] = g_P2[j * Hn + f];
    }
    __shared__ float xs[32][NDn];
    int n0 = blockIdx.x * 32;
    for (int i = f; i < 32 * NDn; i += 128)
        xs[i / NDn][i % NDn] = x_g[(n0 + i / NDn) * NDn + i % NDn];
    __syncthreads();
    float* u1 = g_y;
    float* u2 = g_y + (size_t)NGn * Hn;
    for (int nn = 0; nn < 32; nn++) {
        float a1 = 0.f, a2 = 0.f;
#pragma unroll
        for (int j = 0; j < NDn; j++) {
            float xv = xs[nn][j];
            a1 += xv * p1[j];
            a2 += xv * p2[j];
        }
        u1[(n0 + nn) * Hn + f] = a1;
        u2[(n0 + nn) * Hn + f] = a2;
    }
}

// ---------------- initial edge embedding (round-2 float4 version) ----------------
__global__ __launch_bounds__(256) void k_msg(const float* __restrict__ W_msg,
                                             const float* __restrict__ ea,
                                             const float* __restrict__ xlg,
                                             const int* __restrict__ eig) {
    const int lane = threadIdx.x & 31;
    const int warp = threadIdx.x >> 5;
    const int f = lane * 4;
    float4 w3[16], w4[4];
#pragma unroll
    for (int k = 0; k < 16; k++) w3[k] = *(const float4*)&W_msg[(2 * Hn + k) * Hn + f];
#pragma unroll
    for (int k = 0; k < 4; k++) w4[k] = *(const float4*)&W_msg[(2 * Hn + EDn + k) * Hn + f];
    float4 bf = *(const float4*)&g_beff[f];
    const float* u1 = g_y;
    const float* u2 = g_y + (size_t)NGn * Hn;

    int e0 = (blockIdx.x * 8 + warp) * 8;
    for (int it = 0; it < 8; it++) {
        int e = e0 + it;
        int s = eig[e];
        int d = eig[EGn + e];
        float4 acc = bf;
        acc += *(const float4*)&u1[s * Hn + f];
        acc += *(const float4*)&u2[d * Hn + f];
#pragma unroll
        for (int k = 0; k < 4; k++) {
            float4 av = *(const float4*)&ea[e * EDn + k * 4];
            acc += av.x * w3[4 * k + 0];
            acc += av.y * w3[4 * k + 1];
            acc += av.z * w3[4 * k + 2];
            acc += av.w * w3[4 * k + 3];
        }
        float4 xv = *(const float4*)&xlg[e * NBn];
        acc += xv.x * w4[0];
        acc += xv.y * w4[1];
        acc += xv.z * w4[2];
        acc += xv.w * w4[3];
        *(float4*)&g_h[e * Hn + f] = acc;
    }
}

// ---------------- CSR build (line graph, by dst) ----------------
__global__ void k_zero_deg() {
    int i = blockIdx.x * blockDim.x + threadIdx.x;
    if (i < EGn) g_deg[i] = 0;
}
__global__ void k_hist(const int* __restrict__ eilg) {
    int e = blockIdx.x * blockDim.x + threadIdx.x;
    if (e < ELGn) atomicAdd(&g_deg[eilg[ELGn + e]], 1);
}
__global__ void k_scan1() {
    __shared__ int sh[1024];
    int t = threadIdx.x;
    int i = blockIdx.x * 1024 + t;
    sh[t] = g_deg[i];
    __syncthreads();
    for (int ofs = 1; ofs < 1024; ofs <<= 1) {
        int v = (t >= ofs) ? sh[t - ofs] : 0;
        __syncthreads();
        sh[t] += v;
        __syncthreads();
    }
    g_off[i + 1] = sh[t];
    if (t == 1023) g_bsum[blockIdx.x] = sh[1023];
}
__global__ void k_scan2() {
    __shared__ int sh[128];
    int t = threadIdx.x;
    int v = g_bsum[t];
    sh[t] = v;
    __syncthreads();
    for (int ofs = 1; ofs < 128; ofs <<= 1) {
        int w = (t >= ofs) ? sh[t - ofs] : 0;
        __syncthreads();
        sh[t] += w;
        __syncthreads();
    }
    g_bofs[t] = sh[t] - v;
}
__global__ void k_scan3() {
    int i = blockIdx.x * 1024 + threadIdx.x;
    int inc = g_off[i + 1] + g_bofs[i >> 10];
    g_off[i + 1] = inc;
    g_cur[i] = inc - g_deg[i];
    if (i == 0) g_off[0] = 0;
}
__global__ void k_fill(const int* __restrict__ eilg) {
    int e = blockIdx.x * blockDim.x + threadIdx.x;
    if (e < ELGn) {
        int d = eilg[ELGn + e];
        int p = atomicAdd(&g_cur[d], 1);
        g_csr_src[p] = eilg[e];
        g_csr_eid[p] = e;
    }
}

// ---------------- node CSR build ----------------
__global__ void k_nzero() {
    int i = blockIdx.x * blockDim.x + threadIdx.x;
    if (i < NGn) g_ndeg[i] = 0;
}
__global__ void k_nhist(const int* __restrict__ eig) {
    int e = blockIdx.x * blockDim.x + threadIdx.x;
    if (e < EGn) atomicAdd(&g_ndeg[eig[EGn + e]], 1);
}
__global__ void k_nscan1() {
    __shared__ int sh[1024];
    int t = threadIdx.x;
    int i = blockIdx.x * 1024 + t;
    sh[t] = g_ndeg[i];
    __syncthreads();
    for (int ofs = 1; ofs < 1024; ofs <<= 1) {
        int v = (t >= ofs) ? sh[t - ofs] : 0;
        __syncthreads();
        sh[t] += v;
        __syncthreads();
    }
    g_noff[i + 1] = sh[t];
    if (t == 1023) g_nbsum[blockIdx.x] = sh[1023];
}
__global__ void k_nscan2() {
    __shared__ int sh[32];
    int t = threadIdx.x;
    int v = g_nbsum[t];
    sh[t] = v;
    __syncthreads();
    for (int ofs = 1; ofs < 32; ofs <<= 1) {
        int w = (t >= ofs) ? sh[t - ofs] : 0;
        __syncthreads();
        sh[t] += w;
        __syncthreads();
    }
    g_nbofs[t] = sh[t] - v;
}
__global__ void k_nscan3() {
    int i = blockIdx.x * 1024 + threadIdx.x;
    int inc = g_noff[i + 1] + g_nbofs[i >> 10];
    g_noff[i + 1] = inc;
    g_ncur[i] = inc - g_ndeg[i];
    if (i == 0) g_noff[0] = 0;
}
__global__ void k_nfill(const int* __restrict__ eig) {
    int e = blockIdx.x * blockDim.x + threadIdx.x;
    if (e < EGn) {
        int d = eig[EGn + e];
        int p = atomicAdd(&g_ncur[d], 1);
        g_ncsr[p] = e;
    }
}

// ---------------- pass A: per-CSR-slot message m -> g_m (CSR order, coalesced writes) ----------------
__global__ __launch_bounds__(256) void k_edge_m(
    const float* __restrict__ W_nb, const float* __restrict__ b_nb,
    const float* __restrict__ W_eb, const float* __restrict__ b_eb,
    const float* __restrict__ basis, const float* __restrict__ attr,
    int layer, const float* __restrict__ gamma, const float* __restrict__ beta) {
    const int lane = threadIdx.x & 31;
    const int f = lane * 4;
    const int gw = (blockIdx.x * blockDim.x + threadIdx.x) >> 5;
    const int nw = (gridDim.x * blockDim.x) >> 5;
    const int doAct = layer > 0;

    float4 wnb0 = *(const float4*)&W_nb[0 * Hn + f];
    float4 wnb1 = *(const float4*)&W_nb[1 * Hn + f];
    float4 wnb2 = *(const float4*)&W_nb[2 * Hn + f];
    float4 wnb3 = *(const float4*)&W_nb[3 * Hn + f];
    float4 web0 = *(const float4*)&W_eb[0 * Hn + f];
    float4 web1 = *(const float4*)&W_eb[1 * Hn + f];
    float4 web2 = *(const float4*)&W_eb[2 * Hn + f];
    float4 web3 = *(const float4*)&W_eb[3 * Hn + f];
    float4 bnb = *(const float4*)&b_nb[f];
    float4 beb = *(const float4*)&b_eb[f];
    float4 gg = f4zero(), bb = f4zero();
    if (doAct) {
        gg = BNINV * (*(const float4*)&gamma[(layer - 1) * Hn + f]);
        bb = *(const float4*)&beta[(layer - 1) * Hn + f];
    }

    // 2 slots per warp iteration: batch independent loads for MLP
    for (int o = gw * 2; o < ELGn; o += nw * 2) {
        int sv0 = g_csr_src[o],     sv1 = g_csr_src[o + 1];
        int e0  = g_csr_eid[o],     e1  = g_csr_eid[o + 1];
        float4 x0 = *(const float4*)&g_h[(size_t)sv0 * Hn + f];
        float4 x1 = *(const float4*)&g_h[(size_t)sv1 * Hn + f];
        float4 bs0 = *(const float4*)&basis[sv0 * 4];
        float4 bs1 = *(const float4*)&basis[sv1 * 4];
        float4 at0 = *(const float4*)&attr[e0 * 4];
        float4 at1 = *(const float4*)&attr[e1 * 4];
        if (doAct) {
            x0.x = fmaxf(x0.x * gg.x + bb.x, 0.f);
            x0.y = fmaxf(x0.y * gg.y + bb.y, 0.f);
            x0.z = fmaxf(x0.z * gg.z + bb.z, 0.f);
            x0.w = fmaxf(x0.w * gg.w + bb.w, 0.f);
            x1.x = fmaxf(x1.x * gg.x + bb.x, 0.f);
            x1.y = fmaxf(x1.y * gg.y + bb.y, 0.f);
            x1.z = fmaxf(x1.z * gg.z + bb.z, 0.f);
            x1.w = fmaxf(x1.w * gg.w + bb.w, 0.f);
        }
        float4 nb0 = bnb + bs0.x * wnb0 + bs0.y * wnb1 + bs0.z * wnb2 + bs0.w * wnb3;
        float4 eb0 = beb + at0.x * web0 + at0.y * web1 + at0.z * web2 + at0.w * web3;
        float4 nb1 = bnb + bs1.x * wnb0 + bs1.y * wnb1 + bs1.z * wnb2 + bs1.w * wnb3;
        float4 eb1 = beb + at1.x * web0 + at1.y * web1 + at1.z * web2 + at1.w * web3;
        float4 m0, m1;
        m0.x = fmaxf(x0.x * nb0.x * eb0.x, 0.f) + EPSM;
        m0.y = fmaxf(x0.y * nb0.y * eb0.y, 0.f) + EPSM;
        m0.z = fmaxf(x0.z * nb0.z * eb0.z, 0.f) + EPSM;
        m0.w = fmaxf(x0.w * nb0.w * eb0.w, 0.f) + EPSM;
        m1.x = fmaxf(x1.x * nb1.x * eb1.x, 0.f) + EPSM;
        m1.y = fmaxf(x1.y * nb1.y * eb1.y, 0.f) + EPSM;
        m1.z = fmaxf(x1.z * nb1.z * eb1.z, 0.f) + EPSM;
        m1.w = fmaxf(x1.w * nb1.w * eb1.w, 0.f) + EPSM;
        *(float4*)&g_m[(size_t)o * Hn + f] = m0;
        *(float4*)&g_m[(size_t)(o + 1) * Hn + f] = m1;
    }
}

// ---------------- pass B fused: softmax-agg (streaming m) + bf16 split + MMA + epilogue ----------------
#define PADK  136
#define ROWB  (PADK * 2)          // 272 bytes per row
#define ABUF  (128 * ROWB)        // 34816 bytes per tile
#define AGG_SMEM (4 * ABUF + 65536)  // + fp32 residual tile = 204800

__global__ __launch_bounds__(256) void k_agg_gemm(
    const float* __restrict__ bias, int layer, int addRes,
    const float* __restrict__ tvals,
    const float* __restrict__ gamma, const float* __restrict__ beta) {
    extern __shared__ char smem[];
    const uint32_t sb = smem_u32(smem);
    const int tid = threadIdx.x;
    const int wid = tid >> 5;
    const int lane = tid & 31;
    const int row0 = blockIdx.x * 128;
    const uint32_t OF_AH = 0, OF_AL = ABUF, OF_BH = 2 * ABUF, OF_BL = 3 * ABUF, OF_R = 4 * ABUF;
    const int doAct = layer > 0;
    const float t = tvals[layer];

    // ---- B tiles (pre-split W^T) ----
    {
        const uint4* WH = (const uint4*)(g_WtH + layer * Hn * Hn);
        const uint4* WL = (const uint4*)(g_WtL + layer * Hn * Hn);
#pragma unroll
        for (int i = 0; i < 8; i++) {
            int u = tid + i * 256;
            int r = u >> 4, cb = u & 15;
            *(uint4*)(smem + OF_BH + r * ROWB + cb * 16) = WH[u];
            *(uint4*)(smem + OF_BL + r * ROWB + cb * 16) = WL[u];
        }
    }

    // ---- A tiles: aggregation fused with bf16 hi/lo split ----
    {
        const int f = lane * 4;
        float4 gg = f4zero(), bb = f4zero();
        if (doAct) {
            gg = BNINV * (*(const float4*)&gamma[(layer - 1) * Hn + f]);
            bb = *(const float4*)&beta[(layer - 1) * Hn + f];
        }
#pragma unroll 2
        for (int rr = 0; rr < 16; rr++) {
            int r = wid * 16 + rr;
            int sg = row0 + r;
            int o0 = g_off[sg], o1 = g_off[sg + 1];
            float4 num = f4zero(), den = f4zero();
            for (int o = o0; o < o1; o++) {
                float4 mv = *(const float4*)&g_m[(size_t)o * Hn + f];
                float4 ex;
                ex.x = __expf(fminf(mv.x * t, 60.f));
                ex.y = __expf(fminf(mv.y * t, 60.f));
                ex.z = __expf(fminf(mv.z * t, 60.f));
                ex.w = __expf(fminf(mv.w * t, 60.f));
                den += ex;
                num.x += ex.x * mv.x;
                num.y += ex.y * mv.y;
                num.z += ex.z * mv.z;
                num.w += ex.w * mv.w;
            }
            float4 raw = *(const float4*)&g_h[(size_t)sg * Hn + f];
            *(float4*)(smem + OF_R + r * 512 + f * 4) = raw;   // residual cache
            float4 xs = raw;
            if (doAct) {
                xs.x = fmaxf(xs.x * gg.x + bb.x, 0.f);
                xs.y = fmaxf(xs.y * gg.y + bb.y, 0.f);
                xs.z = fmaxf(xs.z * gg.z + bb.z, 0.f);
                xs.w = fmaxf(xs.w * gg.w + bb.w, 0.f);
            }
            float4 a = xs;
            if (o1 > o0) {
                a.x += num.x / den.x;
                a.y += num.y / den.y;
                a.z += num.z / den.z;
                a.w += num.w / den.w;
            }
            // split to bf16 hi/lo
            float av[4] = {a.x, a.y, a.z, a.w};
            uint32_t hs[4], ls[4];
#pragma unroll
            for (int j = 0; j < 4; j++) {
                __nv_bfloat16 h = __float2bfloat16_rn(av[j]);
                float rres = av[j] - __bfloat162float(h);
                hs[j] = (uint32_t)__bfloat16_as_ushort(h);
                ls[j] = (uint32_t)__bfloat16_as_ushort(__float2bfloat16_rn(rres));
            }
            uint2 hi = make_uint2(hs[0] | (hs[1] << 16), hs[2] | (hs[3] << 16));
            uint2 lo = make_uint2(ls[0] | (ls[1] << 16), ls[2] | (ls[3] << 16));
            *(uint2*)(smem + OF_AH + r * ROWB + f * 2) = hi;
            *(uint2*)(smem + OF_AL + r * ROWB + f * 2) = lo;
        }
    }
    __syncthreads();

    // ---- MMA ----
    const int wm = wid >> 1;
    const int wn = wid & 1;
    const int rA = wm * 32;
    const int nBase = wn * 64;

    float acc[2][8][4];
#pragma unroll
    for (int a = 0; a < 2; a++)
#pragma unroll
        for (int b = 0; b < 8; b++)
#pragma unroll
            for (int c = 0; c < 4; c++) acc[a][b][c] = 0.f;

    const int a_row = lane & 15;
    const int a_kof = (lane >> 4) * 8;
    const int b_row = ((lane >> 4) << 3) + (lane & 7);
    const int b_kof = ((lane >> 3) & 1) * 8;

#pragma unroll
    for (int ks = 0; ks < 8; ks++) {
        const int k0 = ks * 16;
        uint32_t aH[2][4], aL[2][4], bH[4][4], bL[4][4];
#pragma unroll
        for (int mt = 0; mt < 2; mt++) {
            uint32_t ad = sb + OF_AH + (uint32_t)((rA + mt * 16 + a_row) * ROWB + (k0 + a_kof) * 2);
            ldsm_x4(aH[mt], ad);
            ldsm_x4(aL[mt], ad + ABUF);
        }
#pragma unroll
        for (int np = 0; np < 4; np++) {
            uint32_t bd = sb + OF_BH + (uint32_t)((nBase + np * 16 + b_row) * ROWB + (k0 + b_kof) * 2);
            ldsm_x4(bH[np], bd);
            ldsm_x4(bL[np], bd + ABUF);
        }
#pragma unroll
        for (int mt = 0; mt < 2; mt++)
#pragma unroll
            for (int np = 0; np < 4; np++) {
                mma_bf16(acc[mt][2 * np],     aH[mt], &bH[np][0]);
                mma_bf16(acc[mt][2 * np + 1], aH[mt], &bH[np][2]);
                mma_bf16(acc[mt][2 * np],     aL[mt], &bH[np][0]);
                mma_bf16(acc[mt][2 * np + 1], aL[mt], &bH[np][2]);
                mma_bf16(acc[mt][2 * np],     aH[mt], &bL[np][0]);
                mma_bf16(acc[mt][2 * np + 1], aH[mt], &bL[np][2]);
            }
    }

    // ---- epilogue: bias (+residual from SMEM) -> g_h ----
    const int tg = lane >> 2, tig = lane & 3;
#pragma unroll
    for (int mt = 0; mt < 2; mt++)
#pragma unroll
        for (int nt = 0; nt < 8; nt++) {
            int col = nBase + nt * 8 + tig * 2;
            float2 bv = *(const float2*)&bias[col];
            int rt1 = rA + mt * 16 + tg;
            int rt2 = rt1 + 8;
            float2 o1 = make_float2(acc[mt][nt][0] + bv.x, acc[mt][nt][1] + bv.y);
            float2 o2 = make_float2(acc[mt][nt][2] + bv.x, acc[mt][nt][3] + bv.y);
            if (addRes) {
                float2 q1 = *(const float2*)(smem + OF_R + rt1 * 512 + col * 4);
                float2 q2 = *(const float2*)(smem + OF_R + rt2 * 512 + col * 4);
                o1.x += q1.x; o1.y += q1.y;
                o2.x += q2.x; o2.y += q2.y;
            }
            *(float2*)&g_h[(size_t)(row0 + rt1) * Hn + col] = o1;
            *(float2*)&g_h[(size_t)(row0 + rt2) * Hn + col] = o2;
        }
}

// ---------------- final BN + node gather ----------------
__global__ __launch_bounds__(256) void k_nemb(const float* __restrict__ gamma,
                                              const float* __restrict__ beta) {
    const int lane = threadIdx.x & 31;
    const int wid = threadIdx.x >> 5;
    const int f = lane * 4;
    const int n = blockIdx.x * 8 + wid;

    float4 gs, bt;
    gs.x = gamma[(Ln - 1) * Hn + f + 0] * BNINV;
    gs.y = gamma[(Ln - 1) * Hn + f + 1] * BNINV;
    gs.z = gamma[(Ln - 1) * Hn + f + 2] * BNINV;
    gs.w = gamma[(Ln - 1) * Hn + f + 3] * BNINV;
    bt = *(const float4*)&beta[(Ln - 1) * Hn + f];

    int o0 = g_noff[n], o1 = g_noff[n + 1];
    float4 acc = f4zero();
    for (int o = o0; o < o1; o++) {
        int e = g_ncsr[o];
        acc += *(const float4*)&g_h[(size_t)e * Hn + f];
    }
    float deg = (float)(o1 - o0);
    float4 outv;
    outv.x = gs.x * acc.x + deg * bt.x;
    outv.y = gs.y * acc.y + deg * bt.y;
    outv.z = gs.z * acc.z + deg * bt.z;
    outv.w = gs.w * acc.w + deg * bt.w;
    *(float4*)&g_nemb[(size_t)n * Hn + f] = outv;
}

// ---------------- pooling + prediction head ----------------
__global__ __launch_bounds__(128) void k_pool_pred(const int* __restrict__ batch,
                                                   const float* __restrict__ W_pred,
                                                   const float* __restrict__ b_pred,
                                                   float* __restrict__ out) {
    int b = blockIdx.x;
    int f = threadIdx.x;
    int lo = 0, hi = NGn;
    while (lo < hi) { int mid = (lo + hi) >> 1; if (batch[mid] < b) lo = mid + 1; else hi = mid; }
    int start = lo;
    hi = NGn;
    while (lo < hi) { int mid = (lo + hi) >> 1; if (batch[mid] < b + 1) lo = mid + 1; else hi = mid; }
    int end = lo;
    float acc = 0.f;
    for (int n = start; n < end; n++) acc += g_nemb[n * Hn + f];
    __shared__ float mean[Hn];
    mean[f] = acc / fmaxf((float)(end - start), 1.0f);
    __syncthreads();
    if (f < TKn) {
        float o = b_pred[f];
        for (int k = 0; k < Hn; k++) o += mean[k] * W_pred[k * TKn + f];
        out[b * TKn + f] = o;
    }
}

// ---------------- launch ----------------
extern "C" void kernel_launch(void* const* d_in, const int* in_sizes, int n_in,
                              void* d_out, int out_size) {
    const float* x_g      = (const float*)d_in[0];
    const float* ea_g     = (const float*)d_in[1];
    const float* x_lg     = (const float*)d_in[2];
    const float* basis    = (const float*)d_in[3];
    const float* attr_lg  = (const float*)d_in[4];
    const int*   eig      = (const int*)d_in[5];
    const int*   eilg     = (const int*)d_in[6];
    const int*   batch    = (const int*)d_in[7];
    const float* W_enc    = (const float*)d_in[8];
    const float* b_enc    = (const float*)d_in[9];
    const float* W_msg    = (const float*)d_in[10];
    const float* b_msg    = (const float*)d_in[11];
    const float* W_nb     = (const float*)d_in[12];
    const float* b_nb     = (const float*)d_in[13];
    const float* W_eb     = (const float*)d_in[14];
    const float* b_eb     = (const float*)d_in[15];
    const float* W_gcn    = (const float*)d_in[16];
    const float* b_gcn    = (const float*)d_in[17];
    const float* t_vals   = (const float*)d_in[18];
    const float* gamma    = (const float*)d_in[19];
    const float* beta     = (const float*)d_in[20];
    const float* W_pred   = (const float*)d_in[21];
    const float* b_pred   = (const float*)d_in[22];
    float* out = (float*)d_out;

    cudaFuncSetAttribute(k_agg_gemm, cudaFuncAttributeMaxDynamicSharedMemorySize, AGG_SMEM);

    // prep
    k_params<<<65, 128>>>(W_enc, W_msg, b_enc, b_msg);
    k_wt<<<(Ln * Hn * Hn) / 256, 256>>>(W_gcn);
    k_u<<<NGn / 32, 128>>>(x_g);
    k_msg<<<EGn / 64, 256>>>(W_msg, ea_g, x_lg, eig);

    // CSR by destination line-graph node
    k_zero_deg<<<EGn / 256, 256>>>();
    k_hist<<<ELGn / 256, 256>>>(eilg);
    k_scan1<<<128, 1024>>>();
    k_scan2<<<1, 128>>>();
    k_scan3<<<128, 1024>>>();
    k_fill<<<ELGn / 256, 256>>>(eilg);

    // node CSR (dst_g) for final gather
    k_nzero<<<NGn / 256, 256>>>();
    k_nhist<<<EGn / 256, 256>>>(eig);
    k_nscan1<<<32, 1024>>>();
    k_nscan2<<<1, 32>>>();
    k_nscan3<<<32, 1024>>>();
    k_nfill<<<EGn / 256, 256>>>(eig);

    // 4 GENConv layers: pass A (messages) + fused agg+GEMM
    for (int l = 0; l < Ln; l++) {
        k_edge_m<<<4096, 256>>>(W_nb, b_nb, W_eb, b_eb, basis, attr_lg,
                                l, gamma, beta);
        k_agg_gemm<<<EGn / 128, 256, AGG_SMEM>>>(b_gcn + l * Hn, l, l > 0 ? 1 : 0,
                                                 t_vals, gamma, beta);
    }

    // final BN + gather to graph nodes, pool per batch (sorted), predict
    k_nemb<<<NGn / 8, 256>>>(gamma, beta);
    k_pool_pred<<<Bn, 128>>>(batch, W_pred, b_pred, out);
}

// round 11
// speedup vs baseline: 1.2449x; 1.2449x over previous
#include <cuda_runtime.h>
#include <cuda_bf16.h>
#include <cstdint>

// ---------------- problem constants ----------------
#define NGn   32768
#define EGn   131072
#define ELGn  262144
#define Hn    128
#define NDn   32
#define EDn   16
#define NBn   4
#define Ln    4
#define Bn    256
#define TKn   10
#define EPSM  1e-7f
#define BNINV 0.9999950000374997f   // 1/sqrt(1+1e-5)

// ---------------- device scratch (no allocs allowed) ----------------
static __device__ float g_h[EGn * Hn];      // ping buffer (64 MiB)
static __device__ float g_y[EGn * Hn];      // pong buffer / u1,u2 during prep (64 MiB)
static __device__ float g_P1[NDn * Hn];
static __device__ float g_P2[NDn * Hn];
static __device__ float g_beff[Hn];
static __device__ int   g_deg[EGn];
static __device__ int   g_off[EGn + 1];
static __device__ int   g_cur[EGn];
static __device__ int   g_bsum[128];
static __device__ int   g_bofs[128];
static __device__ int   g_csr_src[ELGn];
static __device__ int   g_csr_eid[ELGn];
static __device__ float g_nemb[NGn * Hn];   // 16 MiB
static __device__ __nv_bfloat16 g_WtH[Ln * Hn * Hn];  // W transposed, bf16 hi
static __device__ __nv_bfloat16 g_WtL[Ln * Hn * Hn];  // W transposed, bf16 lo
// node CSR (dst_g -> edge ids)
static __device__ int   g_ndeg[NGn];
static __device__ int   g_noff[NGn + 1];
static __device__ int   g_ncur[NGn];
static __device__ int   g_ncsr[EGn];
static __device__ int   g_nbsum[32];
static __device__ int   g_nbofs[32];

// ---------------- small vector helpers ----------------
__device__ __forceinline__ float4 f4zero() { return make_float4(0.f, 0.f, 0.f, 0.f); }
__device__ __forceinline__ float4 operator+(float4 a, float4 b) {
    return make_float4(a.x + b.x, a.y + b.y, a.z + b.z, a.w + b.w);
}
__device__ __forceinline__ void operator+=(float4& a, float4 b) {
    a.x += b.x; a.y += b.y; a.z += b.z; a.w += b.w;
}
__device__ __forceinline__ float4 operator*(float a, float4 b) {
    return make_float4(a * b.x, a * b.y, a * b.z, a * b.w);
}

// ---------------- portable tensor-core helpers ----------------
__device__ __forceinline__ uint32_t smem_u32(const void* p) {
    uint32_t a;
    asm("{ .reg .u64 t; cvta.to.shared.u64 t, %1; cvt.u32.u64 %0, t; }" : "=r"(a) : "l"(p));
    return a;
}
__device__ __forceinline__ void ldsm_x4(uint32_t* r, uint32_t addr) {
    asm volatile("ldmatrix.sync.aligned.m8n8.x4.shared.b16 {%0,%1,%2,%3}, [%4];"
                 : "=r"(r[0]), "=r"(r[1]), "=r"(r[2]), "=r"(r[3]) : "r"(addr));
}
__device__ __forceinline__ void mma_bf16(float* d, const uint32_t* a, const uint32_t* b) {
    asm volatile("mma.sync.aligned.m16n8k16.row.col.f32.bf16.bf16.f32 "
                 "{%0,%1,%2,%3}, {%4,%5,%6,%7}, {%8,%9}, {%0,%1,%2,%3};"
                 : "+f"(d[0]), "+f"(d[1]), "+f"(d[2]), "+f"(d[3])
                 : "r"(a[0]), "r"(a[1]), "r"(a[2]), "r"(a[3]), "r"(b[0]), "r"(b[1]));
}

// ---------------- param prep ----------------
__global__ void k_params(const float* __restrict__ W_enc, const float* __restrict__ W_msg,
                         const float* __restrict__ b_enc, const float* __restrict__ b_msg) {
    int f = threadIdx.x;
    int b = blockIdx.x;
    if (b < 32) {
        float acc = 0.f;
        for (int k = 0; k < Hn; k++) acc += W_enc[b * Hn + k] * W_msg[k * Hn + f];
        g_P1[b * Hn + f] = acc;
    } else if (b < 64) {
        int j = b - 32;
        float acc = 0.f;
        for (int k = 0; k < Hn; k++) acc += W_enc[j * Hn + k] * W_msg[(Hn + k) * Hn + f];
        g_P2[j * Hn + f] = acc;
    } else {
        float acc = b_msg[f];
        for (int k = 0; k < Hn; k++)
            acc += b_enc[k] * (W_msg[k * Hn + f] + W_msg[(Hn + k) * Hn + f]);
        g_beff[f] = acc;
    }
}

// ---------------- W transpose + bf16 hi/lo split ----------------
__global__ void k_wt(const float* __restrict__ W_gcn) {
    int i = blockIdx.x * blockDim.x + threadIdx.x;
    int l = i >> 14;
    int rem = i & 16383;
    int n = rem >> 7, k = rem & 127;
    float w = W_gcn[l * Hn * Hn + k * Hn + n];
    __nv_bfloat16 h = __float2bfloat16_rn(w);
    float r = w - __bfloat162float(h);
    g_WtH[i] = h;
    g_WtL[i] = __float2bfloat16_rn(r);
}

// ---------------- per-node u1/u2 ----------------
__global__ __launch_bounds__(128) void k_u(const float* __restrict__ x_g) {
    int f = threadIdx.x;
    float p1[NDn], p2[NDn];
#pragma unroll
    for (int j = 0; j < NDn; j++) {
        p1[j] = g_P1[j * Hn + f];
        p2[j] = g_P2[j * Hn + f];
    }
    __shared__ float xs[32][NDn];
    int n0 = blockIdx.x * 32;
    for (int i = f; i < 32 * NDn; i += 128)
        xs[i / NDn][i % NDn] = x_g[(n0 + i / NDn) * NDn + i % NDn];
    __syncthreads();
    float* u1 = g_y;
    float* u2 = g_y + (size_t)NGn * Hn;
    for (int nn = 0; nn < 32; nn++) {
        float a1 = 0.f, a2 = 0.f;
#pragma unroll
        for (int j = 0; j < NDn; j++) {
            float xv = xs[nn][j];
            a1 += xv * p1[j];
            a2 += xv * p2[j];
        }
        u1[(n0 + nn) * Hn + f] = a1;
        u2[(n0 + nn) * Hn + f] = a2;
    }
}

// ---------------- initial edge embedding (float4, 256 threads — measured best) ----------------
__global__ __launch_bounds__(256) void k_msg(const float* __restrict__ W_msg,
                                             const float* __restrict__ ea,
                                             const float* __restrict__ xlg,
                                             const int* __restrict__ eig) {
    const int lane = threadIdx.x & 31;
    const int warp = threadIdx.x >> 5;
    const int f = lane * 4;
    float4 w3[16], w4[4];
#pragma unroll
    for (int k = 0; k < 16; k++) w3[k] = *(const float4*)&W_msg[(2 * Hn + k) * Hn + f];
#pragma unroll
    for (int k = 0; k < 4; k++) w4[k] = *(const float4*)&W_msg[(2 * Hn + EDn + k) * Hn + f];
    float4 bf = *(const float4*)&g_beff[f];
    const float* u1 = g_y;
    const float* u2 = g_y + (size_t)NGn * Hn;

    int e0 = (blockIdx.x * 8 + warp) * 8;
    for (int it = 0; it < 8; it++) {
        int e = e0 + it;
        int s = eig[e];
        int d = eig[EGn + e];
        float4 acc = bf;
        acc += *(const float4*)&u1[s * Hn + f];
        acc += *(const float4*)&u2[d * Hn + f];
#pragma unroll
        for (int k = 0; k < 4; k++) {
            float4 av = *(const float4*)&ea[e * EDn + k * 4];
            acc += av.x * w3[4 * k + 0];
            acc += av.y * w3[4 * k + 1];
            acc += av.z * w3[4 * k + 2];
            acc += av.w * w3[4 * k + 3];
        }
        float4 xv = *(const float4*)&xlg[e * NBn];
        acc += xv.x * w4[0];
        acc += xv.y * w4[1];
        acc += xv.z * w4[2];
        acc += xv.w * w4[3];
        *(float4*)&g_h[e * Hn + f] = acc;
    }
}

// ---------------- CSR builds (both CSRs, merged kernels) ----------------
__global__ void k_zero_all() {
    int i = blockIdx.x * blockDim.x + threadIdx.x;
    if (i < EGn) g_deg[i] = 0;
    if (i < NGn) g_ndeg[i] = 0;
}
__global__ void k_hist_all(const int* __restrict__ eilg, const int* __restrict__ eig) {
    int e = blockIdx.x * blockDim.x + threadIdx.x;
    if (e < ELGn) atomicAdd(&g_deg[eilg[ELGn + e]], 1);
    if (e < EGn) atomicAdd(&g_ndeg[eig[EGn + e]], 1);
}
__global__ void k_scan1() {
    __shared__ int sh[1024];
    int t = threadIdx.x;
    int i = blockIdx.x * 1024 + t;
    sh[t] = g_deg[i];
    __syncthreads();
    for (int ofs = 1; ofs < 1024; ofs <<= 1) {
        int v = (t >= ofs) ? sh[t - ofs] : 0;
        __syncthreads();
        sh[t] += v;
        __syncthreads();
    }
    g_off[i + 1] = sh[t];
    if (t == 1023) g_bsum[blockIdx.x] = sh[1023];
}
__global__ void k_scan2() {
    __shared__ int sh[128];
    int t = threadIdx.x;
    int v = g_bsum[t];
    sh[t] = v;
    __syncthreads();
    for (int ofs = 1; ofs < 128; ofs <<= 1) {
        int w = (t >= ofs) ? sh[t - ofs] : 0;
        __syncthreads();
        sh[t] += w;
        __syncthreads();
    }
    g_bofs[t] = sh[t] - v;
}
__global__ void k_nscan1() {
    __shared__ int sh[1024];
    int t = threadIdx.x;
    int i = blockIdx.x * 1024 + t;
    sh[t] = g_ndeg[i];
    __syncthreads();
    for (int ofs = 1; ofs < 1024; ofs <<= 1) {
        int v = (t >= ofs) ? sh[t - ofs] : 0;
        __syncthreads();
        sh[t] += v;
        __syncthreads();
    }
    g_noff[i + 1] = sh[t];
    if (t == 1023) g_nbsum[blockIdx.x] = sh[1023];
}
__global__ void k_nscan2() {
    __shared__ int sh[32];
    int t = threadIdx.x;
    int v = g_nbsum[t];
    sh[t] = v;
    __syncthreads();
    for (int ofs = 1; ofs < 32; ofs <<= 1) {
        int w = (t >= ofs) ? sh[t - ofs] : 0;
        __syncthreads();
        sh[t] += w;
        __syncthreads();
    }
    g_nbofs[t] = sh[t] - v;
}
__global__ void k_scan3_all() {  // 128 blocks x 1024; covers both offset arrays
    int i = blockIdx.x * 1024 + threadIdx.x;
    int inc = g_off[i + 1] + g_bofs[i >> 10];
    g_off[i + 1] = inc;
    g_cur[i] = inc - g_deg[i];
    if (i < NGn) {
        int ninc = g_noff[i + 1] + g_nbofs[i >> 10];
        g_noff[i + 1] = ninc;
        g_ncur[i] = ninc - g_ndeg[i];
    }
    if (i == 0) { g_off[0] = 0; g_noff[0] = 0; }
}
__global__ void k_fill_all(const int* __restrict__ eilg, const int* __restrict__ eig) {
    int e = blockIdx.x * blockDim.x + threadIdx.x;
    if (e < ELGn) {
        int d = eilg[ELGn + e];
        int p = atomicAdd(&g_cur[d], 1);
        g_csr_src[p] = eilg[e];
        g_csr_eid[p] = e;
    }
    if (e < EGn) {
        int d = eig[EGn + e];
        int p = atomicAdd(&g_ncur[d], 1);
        g_ncsr[p] = e;
    }
}

// ---------------- fused GENConv layer: gather-agg + softmax + bf16 split + MMA + epilogue ----------------
#define PADK  136
#define ROWB  (PADK * 2)          // 272 bytes per row
#define ABUF  (128 * ROWB)        // 34816 bytes per tile
#define AGG_SMEM (4 * ABUF + 65536)  // + fp32 residual tile = 204800
#define CG_THREADS 512

__global__ __launch_bounds__(CG_THREADS) void k_conv_gemm(
    const float* __restrict__ in, float* __restrict__ outp,
    const float* __restrict__ bias, int layer, int addRes,
    const float* __restrict__ W_nb, const float* __restrict__ b_nb,
    const float* __restrict__ W_eb, const float* __restrict__ b_eb,
    const float* __restrict__ basis, const float* __restrict__ attr,
    const float* __restrict__ tvals,
    const float* __restrict__ gamma, const float* __restrict__ beta) {
    extern __shared__ char smem[];
    const uint32_t sb = smem_u32(smem);
    const int tid = threadIdx.x;
    const int wid = tid >> 5;        // 0..15
    const int lane = tid & 31;
    const int row0 = blockIdx.x * 128;
    const uint32_t OF_AH = 0, OF_AL = ABUF, OF_BH = 2 * ABUF, OF_BL = 3 * ABUF, OF_R = 4 * ABUF;
    const int doAct = layer > 0;
    const float t = tvals[layer];

    // ---- B tiles (pre-split W^T) ----
    {
        const uint4* WH = (const uint4*)(g_WtH + layer * Hn * Hn);
        const uint4* WL = (const uint4*)(g_WtL + layer * Hn * Hn);
#pragma unroll
        for (int i = 0; i < 4; i++) {
            int u = tid + i * CG_THREADS;
            int r = u >> 4, cb = u & 15;
            *(uint4*)(smem + OF_BH + r * ROWB + cb * 16) = WH[u];
            *(uint4*)(smem + OF_BL + r * ROWB + cb * 16) = WL[u];
        }
    }

    // ---- A tiles: on-the-fly aggregation + bf16 hi/lo split (warp-cooperative rows) ----
    {
        const int f = lane * 4;
        float4 wnb0 = *(const float4*)&W_nb[0 * Hn + f];
        float4 wnb1 = *(const float4*)&W_nb[1 * Hn + f];
        float4 wnb2 = *(const float4*)&W_nb[2 * Hn + f];
        float4 wnb3 = *(const float4*)&W_nb[3 * Hn + f];
        float4 web0 = *(const float4*)&W_eb[0 * Hn + f];
        float4 web1 = *(const float4*)&W_eb[1 * Hn + f];
        float4 web2 = *(const float4*)&W_eb[2 * Hn + f];
        float4 web3 = *(const float4*)&W_eb[3 * Hn + f];
        float4 bnb = *(const float4*)&b_nb[f];
        float4 beb = *(const float4*)&b_eb[f];
        float4 gg = f4zero(), bb = f4zero();
        if (doAct) {
            gg = BNINV * (*(const float4*)&gamma[(layer - 1) * Hn + f]);
            bb = *(const float4*)&beta[(layer - 1) * Hn + f];
        }
#pragma unroll 2
        for (int rr = 0; rr < 8; rr++) {
            int r = wid * 8 + rr;
            int sg = row0 + r;
            int o0 = g_off[sg], o1 = g_off[sg + 1];
            float4 num = f4zero(), den = f4zero();
            for (int o = o0; o < o1; o++) {
                int sv = g_csr_src[o];
                int eid = g_csr_eid[o];
                float4 xs = *(const float4*)&in[(size_t)sv * Hn + f];
                float4 bs = *(const float4*)&basis[sv * 4];
                float4 at = *(const float4*)&attr[eid * 4];
                if (doAct) {
                    xs.x = fmaxf(xs.x * gg.x + bb.x, 0.f);
                    xs.y = fmaxf(xs.y * gg.y + bb.y, 0.f);
                    xs.z = fmaxf(xs.z * gg.z + bb.z, 0.f);
                    xs.w = fmaxf(xs.w * gg.w + bb.w, 0.f);
                }
                float4 nb = bnb + bs.x * wnb0 + bs.y * wnb1 + bs.z * wnb2 + bs.w * wnb3;
                float4 eb = beb + at.x * web0 + at.y * web1 + at.z * web2 + at.w * web3;
                float4 m;
                m.x = fmaxf(xs.x * nb.x * eb.x, 0.f) + EPSM;
                m.y = fmaxf(xs.y * nb.y * eb.y, 0.f) + EPSM;
                m.z = fmaxf(xs.z * nb.z * eb.z, 0.f) + EPSM;
                m.w = fmaxf(xs.w * nb.w * eb.w, 0.f) + EPSM;
                float4 ex;
                ex.x = __expf(fminf(m.x * t, 60.f));
                ex.y = __expf(fminf(m.y * t, 60.f));
                ex.z = __expf(fminf(m.z * t, 60.f));
                ex.w = __expf(fminf(m.w * t, 60.f));
                den += ex;
                num.x += ex.x * m.x;
                num.y += ex.y * m.y;
                num.z += ex.z * m.z;
                num.w += ex.w * m.w;
            }
            float4 raw = *(const float4*)&in[(size_t)sg * Hn + f];
            *(float4*)(smem + OF_R + r * 512 + lane * 16) = raw;   // residual cache
            float4 a = raw;
            if (doAct) {
                a.x = fmaxf(a.x * gg.x + bb.x, 0.f);
                a.y = fmaxf(a.y * gg.y + bb.y, 0.f);
                a.z = fmaxf(a.z * gg.z + bb.z, 0.f);
                a.w = fmaxf(a.w * gg.w + bb.w, 0.f);
            }
            if (o1 > o0) {
                a.x += num.x / den.x;
                a.y += num.y / den.y;
                a.z += num.z / den.z;
                a.w += num.w / den.w;
            }
            float av[4] = {a.x, a.y, a.z, a.w};
            uint32_t hs[4], ls[4];
#pragma unroll
            for (int j = 0; j < 4; j++) {
                __nv_bfloat16 h = __float2bfloat16_rn(av[j]);
                float rres = av[j] - __bfloat162float(h);
                hs[j] = (uint32_t)__bfloat16_as_ushort(h);
                ls[j] = (uint32_t)__bfloat16_as_ushort(__float2bfloat16_rn(rres));
            }
            uint2 hi = make_uint2(hs[0] | (hs[1] << 16), hs[2] | (hs[3] << 16));
            uint2 lo = make_uint2(ls[0] | (ls[1] << 16), ls[2] | (ls[3] << 16));
            *(uint2*)(smem + OF_AH + r * ROWB + f * 2) = hi;
            *(uint2*)(smem + OF_AL + r * ROWB + f * 2) = lo;
        }
    }
    __syncthreads();

    // ---- MMA: 16 warps, 32x32 output tile each ----
    const int wm = wid >> 2;
    const int wn = wid & 3;
    const int rA = wm * 32;
    const int nBase = wn * 32;

    float acc[2][4][4];
#pragma unroll
    for (int a = 0; a < 2; a++)
#pragma unroll
        for (int b = 0; b < 4; b++)
#pragma unroll
            for (int c = 0; c < 4; c++) acc[a][b][c] = 0.f;

    const int a_row = lane & 15;
    const int a_kof = (lane >> 4) * 8;
    const int b_row = ((lane >> 4) << 3) + (lane & 7);
    const int b_kof = ((lane >> 3) & 1) * 8;

#pragma unroll
    for (int ks = 0; ks < 8; ks++) {
        const int k0 = ks * 16;
        uint32_t aH[2][4], aL[2][4], bH[2][4], bL[2][4];
#pragma unroll
        for (int mt = 0; mt < 2; mt++) {
            uint32_t ad = sb + OF_AH + (uint32_t)((rA + mt * 16 + a_row) * ROWB + (k0 + a_kof) * 2);
            ldsm_x4(aH[mt], ad);
            ldsm_x4(aL[mt], ad + ABUF);
        }
#pragma unroll
        for (int np = 0; np < 2; np++) {
            uint32_t bd = sb + OF_BH + (uint32_t)((nBase + np * 16 + b_row) * ROWB + (k0 + b_kof) * 2);
            ldsm_x4(bH[np], bd);
            ldsm_x4(bL[np], bd + ABUF);
        }
#pragma unroll
        for (int mt = 0; mt < 2; mt++)
#pragma unroll
            for (int np = 0; np < 2; np++) {
                mma_bf16(acc[mt][2 * np],     aH[mt], &bH[np][0]);
                mma_bf16(acc[mt][2 * np + 1], aH[mt], &bH[np][2]);
                mma_bf16(acc[mt][2 * np],     aL[mt], &bH[np][0]);
                mma_bf16(acc[mt][2 * np + 1], aL[mt], &bH[np][2]);
                mma_bf16(acc[mt][2 * np],     aH[mt], &bL[np][0]);
                mma_bf16(acc[mt][2 * np + 1], aH[mt], &bL[np][2]);
            }
    }

    // ---- epilogue: bias (+residual from SMEM) -> out ----
    const int tg = lane >> 2, tig = lane & 3;
#pragma unroll
    for (int mt = 0; mt < 2; mt++)
#pragma unroll
        for (int nt = 0; nt < 4; nt++) {
            int col = nBase + nt * 8 + tig * 2;
            float2 bv = *(const float2*)&bias[col];
            int rt1 = rA + mt * 16 + tg;
            int rt2 = rt1 + 8;
            float2 o1 = make_float2(acc[mt][nt][0] + bv.x, acc[mt][nt][1] + bv.y);
            float2 o2 = make_float2(acc[mt][nt][2] + bv.x, acc[mt][nt][3] + bv.y);
            if (addRes) {
                float2 q1 = *(const float2*)(smem + OF_R + rt1 * 512 + col * 4);
                float2 q2 = *(const float2*)(smem + OF_R + rt2 * 512 + col * 4);
                o1.x += q1.x; o1.y += q1.y;
                o2.x += q2.x; o2.y += q2.y;
            }
            *(float2*)&outp[(size_t)(row0 + rt1) * Hn + col] = o1;
            *(float2*)&outp[(size_t)(row0 + rt2) * Hn + col] = o2;
        }
}

// ---------------- final BN + node gather (reads g_h = layer-3 output) ----------------
__global__ __launch_bounds__(256) void k_nemb(const float* __restrict__ gamma,
                                              const float* __restrict__ beta) {
    const int lane = threadIdx.x & 31;
    const int wid = threadIdx.x >> 5;
    const int f = lane * 4;
    const int n = blockIdx.x * 8 + wid;

    float4 gs, bt;
    gs.x = gamma[(Ln - 1) * Hn + f + 0] * BNINV;
    gs.y = gamma[(Ln - 1) * Hn + f + 1] * BNINV;
    gs.z = gamma[(Ln - 1) * Hn + f + 2] * BNINV;
    gs.w = gamma[(Ln - 1) * Hn + f + 3] * BNINV;
    bt = *(const float4*)&beta[(Ln - 1) * Hn + f];

    int o0 = g_noff[n], o1 = g_noff[n + 1];
    float4 acc = f4zero();
    for (int o = o0; o < o1; o++) {
        int e = g_ncsr[o];
        acc += *(const float4*)&g_h[(size_t)e * Hn + f];
    }
    float deg = (float)(o1 - o0);
    float4 outv;
    outv.x = gs.x * acc.x + deg * bt.x;
    outv.y = gs.y * acc.y + deg * bt.y;
    outv.z = gs.z * acc.z + deg * bt.z;
    outv.w = gs.w * acc.w + deg * bt.w;
    *(float4*)&g_nemb[(size_t)n * Hn + f] = outv;
}

// ---------------- pooling + prediction head ----------------
__global__ __launch_bounds__(128) void k_pool_pred(const int* __restrict__ batch,
                                                   const float* __restrict__ W_pred,
                                                   const float* __restrict__ b_pred,
                                                   float* __restrict__ out) {
    int b = blockIdx.x;
    int f = threadIdx.x;
    int lo = 0, hi = NGn;
    while (lo < hi) { int mid = (lo + hi) >> 1; if (batch[mid] < b) lo = mid + 1; else hi = mid; }
    int start = lo;
    hi = NGn;
    while (lo < hi) { int mid = (lo + hi) >> 1; if (batch[mid] < b + 1) lo = mid + 1; else hi = mid; }
    int end = lo;
    float acc = 0.f;
    for (int n = start; n < end; n++) acc += g_nemb[n * Hn + f];
    __shared__ float mean[Hn];
    mean[f] = acc / fmaxf((float)(end - start), 1.0f);
    __syncthreads();
    if (f < TKn) {
        float o = b_pred[f];
        for (int k = 0; k < Hn; k++) o += mean[k] * W_pred[k * TKn + f];
        out[b * TKn + f] = o;
    }
}

// ---------------- launch ----------------
extern "C" void kernel_launch(void* const* d_in, const int* in_sizes, int n_in,
                              void* d_out, int out_size) {
    const float* x_g      = (const float*)d_in[0];
    const float* ea_g     = (const float*)d_in[1];
    const float* x_lg     = (const float*)d_in[2];
    const float* basis    = (const float*)d_in[3];
    const float* attr_lg  = (const float*)d_in[4];
    const int*   eig      = (const int*)d_in[5];
    const int*   eilg     = (const int*)d_in[6];
    const int*   batch    = (const int*)d_in[7];
    const float* W_enc    = (const float*)d_in[8];
    const float* b_enc    = (const float*)d_in[9];
    const float* W_msg    = (const float*)d_in[10];
    const float* b_msg    = (const float*)d_in[11];
    const float* W_nb     = (const float*)d_in[12];
    const float* b_nb     = (const float*)d_in[13];
    const float* W_eb     = (const float*)d_in[14];
    const float* b_eb     = (const float*)d_in[15];
    const float* W_gcn    = (const float*)d_in[16];
    const float* b_gcn    = (const float*)d_in[17];
    const float* t_vals   = (const float*)d_in[18];
    const float* gamma    = (const float*)d_in[19];
    const float* beta     = (const float*)d_in[20];
    const float* W_pred   = (const float*)d_in[21];
    const float* b_pred   = (const float*)d_in[22];
    float* out = (float*)d_out;

    static float* s_h = nullptr;
    static float* s_y = nullptr;
    if (!s_h) {
        cudaFuncSetAttribute(k_conv_gemm, cudaFuncAttributeMaxDynamicSharedMemorySize, AGG_SMEM);
        cudaGetSymbolAddress((void**)&s_h, g_h);
        cudaGetSymbolAddress((void**)&s_y, g_y);
    }

    // prep
    k_params<<<65, 128>>>(W_enc, W_msg, b_enc, b_msg);
    k_wt<<<(Ln * Hn * Hn) / 256, 256>>>(W_gcn);
    k_u<<<NGn / 32, 128>>>(x_g);
    k_msg<<<EGn / 64, 256>>>(W_msg, ea_g, x_lg, eig);

    // both CSRs
    k_zero_all<<<EGn / 256, 256>>>();
    k_hist_all<<<ELGn / 256, 256>>>(eilg, eig);
    k_scan1<<<128, 1024>>>();
    k_scan2<<<1, 128>>>();
    k_nscan1<<<32, 1024>>>();
    k_nscan2<<<1, 32>>>();
    k_scan3_all<<<128, 1024>>>();
    k_fill_all<<<ELGn / 256, 256>>>(eilg, eig);

    // 4 fused GENConv layers, ping-pong g_h <-> g_y (layer 3 lands in g_h)
    for (int l = 0; l < Ln; l++) {
        const float* inb = (l & 1) ? s_y : s_h;
        float* outb      = (l & 1) ? s_h : s_y;
        k_conv_gemm<<<EGn / 128, CG_THREADS, AGG_SMEM>>>(
            inb, outb, b_gcn + l * Hn, l, l > 0 ? 1 : 0,
            W_nb, b_nb, W_eb, b_eb, basis, attr_lg, t_vals, gamma, beta);
    }

    // final BN + gather to graph nodes, pool per batch (sorted), predict
    k_nemb<<<NGn / 8, 256>>>(gamma, beta);
    k_pool_pred<<<Bn, 128>>>(batch, W_pred, b_pred, out);
}

// round 12
// speedup vs baseline: 1.6038x; 1.2883x over previous
#include <cuda_runtime.h>
#include <cuda_bf16.h>
#include <cstdint>

// ---------------- problem constants ----------------
#define NGn   32768
#define EGn   131072
#define ELGn  262144
#define Hn    128
#define NDn   32
#define EDn   16
#define NBn   4
#define Ln    4
#define Bn    256
#define TKn   10
#define EPSM  1e-7f
#define BNINV 0.9999950000374997f   // 1/sqrt(1+1e-5)

// ---------------- device scratch (no allocs allowed) ----------------
static __device__ float g_h[EGn * Hn];      // layer state (64 MiB)
static __device__ float g_y[EGn * Hn];      // agg output / u1,u2 during prep (64 MiB)
static __device__ float g_P1[NDn * Hn];
static __device__ float g_P2[NDn * Hn];
static __device__ float g_beff[Hn];
static __device__ int   g_deg[EGn];
static __device__ int   g_off[EGn + 1];
static __device__ int   g_cur[EGn];
static __device__ int   g_bsum[128];
static __device__ int   g_bofs[128];
static __device__ int   g_csr_src[ELGn];
static __device__ int   g_csr_eid[ELGn];
static __device__ float g_nemb[NGn * Hn];   // 16 MiB
static __device__ __nv_bfloat16 g_WtH[Ln * Hn * Hn];  // W transposed, bf16 hi
static __device__ __nv_bfloat16 g_WtL[Ln * Hn * Hn];  // W transposed, bf16 lo
// node CSR (dst_g -> edge ids)
static __device__ int   g_ndeg[NGn];
static __device__ int   g_noff[NGn + 1];
static __device__ int   g_ncur[NGn];
static __device__ int   g_ncsr[EGn];
static __device__ int   g_nbsum[32];
static __device__ int   g_nbofs[32];

// ---------------- small vector helpers ----------------
__device__ __forceinline__ float4 f4zero() { return make_float4(0.f, 0.f, 0.f, 0.f); }
__device__ __forceinline__ float4 operator+(float4 a, float4 b) {
    return make_float4(a.x + b.x, a.y + b.y, a.z + b.z, a.w + b.w);
}
__device__ __forceinline__ void operator+=(float4& a, float4 b) {
    a.x += b.x; a.y += b.y; a.z += b.z; a.w += b.w;
}
__device__ __forceinline__ float4 operator*(float a, float4 b) {
    return make_float4(a * b.x, a * b.y, a * b.z, a * b.w);
}

// ---------------- portable tensor-core helpers ----------------
__device__ __forceinline__ uint32_t smem_u32(const void* p) {
    uint32_t a;
    asm("{ .reg .u64 t; cvta.to.shared.u64 t, %1; cvt.u32.u64 %0, t; }" : "=r"(a) : "l"(p));
    return a;
}
__device__ __forceinline__ void ldsm_x4(uint32_t* r, uint32_t addr) {
    asm volatile("ldmatrix.sync.aligned.m8n8.x4.shared.b16 {%0,%1,%2,%3}, [%4];"
                 : "=r"(r[0]), "=r"(r[1]), "=r"(r[2]), "=r"(r[3]) : "r"(addr));
}
__device__ __forceinline__ void mma_bf16(float* d, const uint32_t* a, const uint32_t* b) {
    asm volatile("mma.sync.aligned.m16n8k16.row.col.f32.bf16.bf16.f32 "
                 "{%0,%1,%2,%3}, {%4,%5,%6,%7}, {%8,%9}, {%0,%1,%2,%3};"
                 : "+f"(d[0]), "+f"(d[1]), "+f"(d[2]), "+f"(d[3])
                 : "r"(a[0]), "r"(a[1]), "r"(a[2]), "r"(a[3]), "r"(b[0]), "r"(b[1]));
}

// ---------------- param prep ----------------
__global__ void k_params(const float* __restrict__ W_enc, const float* __restrict__ W_msg,
                         const float* __restrict__ b_enc, const float* __restrict__ b_msg) {
    int f = threadIdx.x;
    int b = blockIdx.x;
    if (b < 32) {
        float acc = 0.f;
        for (int k = 0; k < Hn; k++) acc += W_enc[b * Hn + k] * W_msg[k * Hn + f];
        g_P1[b * Hn + f] = acc;
    } else if (b < 64) {
        int j = b - 32;
        float acc = 0.f;
        for (int k = 0; k < Hn; k++) acc += W_enc[j * Hn + k] * W_msg[(Hn + k) * Hn + f];
        g_P2[j * Hn + f] = acc;
    } else {
        float acc = b_msg[f];
        for (int k = 0; k < Hn; k++)
            acc += b_enc[k] * (W_msg[k * Hn + f] + W_msg[(Hn + k) * Hn + f]);
        g_beff[f] = acc;
    }
}

// ---------------- W transpose + bf16 hi/lo split ----------------
__global__ void k_wt(const float* __restrict__ W_gcn) {
    int i = blockIdx.x * blockDim.x + threadIdx.x;
    int l = i >> 14;
    int rem = i & 16383;
    int n = rem >> 7, k = rem & 127;
    float w = W_gcn[l * Hn * Hn + k * Hn + n];
    __nv_bfloat16 h = __float2bfloat16_rn(w);
    float r = w - __bfloat162float(h);
    g_WtH[i] = h;
    g_WtL[i] = __float2bfloat16_rn(r);
}

// ---------------- per-node u1/u2 ----------------
__global__ __launch_bounds__(128) void k_u(const float* __restrict__ x_g) {
    int f = threadIdx.x;
    float p1[NDn], p2[NDn];
#pragma unroll
    for (int j = 0; j < NDn; j++) {
        p1[j] = g_P1[j * Hn + f];
        p2[j] = g_P2[j * Hn + f];
    }
    __shared__ float xs[32][NDn];
    int n0 = blockIdx.x * 32;
    for (int i = f; i < 32 * NDn; i += 128)
        xs[i / NDn][i % NDn] = x_g[(n0 + i / NDn) * NDn + i % NDn];
    __syncthreads();
    float* u1 = g_y;
    float* u2 = g_y + (size_t)NGn * Hn;
    for (int nn = 0; nn < 32; nn++) {
        float a1 = 0.f, a2 = 0.f;
#pragma unroll
        for (int j = 0; j < NDn; j++) {
            float xv = xs[nn][j];
            a1 += xv * p1[j];
            a2 += xv * p2[j];
        }
        u1[(n0 + nn) * Hn + f] = a1;
        u2[(n0 + nn) * Hn + f] = a2;
    }
}

// ---------------- initial edge embedding (float4, 256 threads — measured best: 47us) ----------------
__global__ __launch_bounds__(256) void k_msg(const float* __restrict__ W_msg,
                                             const float* __restrict__ ea,
                                             const float* __restrict__ xlg,
                                             const int* __restrict__ eig) {
    const int lane = threadIdx.x & 31;
    const int warp = threadIdx.x >> 5;
    const int f = lane * 4;
    float4 w3[16], w4[4];
#pragma unroll
    for (int k = 0; k < 16; k++) w3[k] = *(const float4*)&W_msg[(2 * Hn + k) * Hn + f];
#pragma unroll
    for (int k = 0; k < 4; k++) w4[k] = *(const float4*)&W_msg[(2 * Hn + EDn + k) * Hn + f];
    float4 bf = *(const float4*)&g_beff[f];
    const float* u1 = g_y;
    const float* u2 = g_y + (size_t)NGn * Hn;

    int e0 = (blockIdx.x * 8 + warp) * 8;
    for (int it = 0; it < 8; it++) {
        int e = e0 + it;
        int s = eig[e];
        int d = eig[EGn + e];
        float4 acc = bf;
        acc += *(const float4*)&u1[s * Hn + f];
        acc += *(const float4*)&u2[d * Hn + f];
#pragma unroll
        for (int k = 0; k < 4; k++) {
            float4 av = *(const float4*)&ea[e * EDn + k * 4];
            acc += av.x * w3[4 * k + 0];
            acc += av.y * w3[4 * k + 1];
            acc += av.z * w3[4 * k + 2];
            acc += av.w * w3[4 * k + 3];
        }
        float4 xv = *(const float4*)&xlg[e * NBn];
        acc += xv.x * w4[0];
        acc += xv.y * w4[1];
        acc += xv.z * w4[2];
        acc += xv.w * w4[3];
        *(float4*)&g_h[e * Hn + f] = acc;
    }
}

// ---------------- CSR builds (both CSRs, merged kernels) ----------------
__global__ void k_zero_all() {
    int i = blockIdx.x * blockDim.x + threadIdx.x;
    if (i < EGn) g_deg[i] = 0;
    if (i < NGn) g_ndeg[i] = 0;
}
__global__ void k_hist_all(const int* __restrict__ eilg, const int* __restrict__ eig) {
    int e = blockIdx.x * blockDim.x + threadIdx.x;
    if (e < ELGn) atomicAdd(&g_deg[eilg[ELGn + e]], 1);
    if (e < EGn) atomicAdd(&g_ndeg[eig[EGn + e]], 1);
}
__global__ void k_scan1() {
    __shared__ int sh[1024];
    int t = threadIdx.x;
    int i = blockIdx.x * 1024 + t;
    sh[t] = g_deg[i];
    __syncthreads();
    for (int ofs = 1; ofs < 1024; ofs <<= 1) {
        int v = (t >= ofs) ? sh[t - ofs] : 0;
        __syncthreads();
        sh[t] += v;
        __syncthreads();
    }
    g_off[i + 1] = sh[t];
    if (t == 1023) g_bsum[blockIdx.x] = sh[1023];
}
__global__ void k_scan2() {
    __shared__ int sh[128];
    int t = threadIdx.x;
    int v = g_bsum[t];
    sh[t] = v;
    __syncthreads();
    for (int ofs = 1; ofs < 128; ofs <<= 1) {
        int w = (t >= ofs) ? sh[t - ofs] : 0;
        __syncthreads();
        sh[t] += w;
        __syncthreads();
    }
    g_bofs[t] = sh[t] - v;
}
__global__ void k_nscan1() {
    __shared__ int sh[1024];
    int t = threadIdx.x;
    int i = blockIdx.x * 1024 + t;
    sh[t] = g_ndeg[i];
    __syncthreads();
    for (int ofs = 1; ofs < 1024; ofs <<= 1) {
        int v = (t >= ofs) ? sh[t - ofs] : 0;
        __syncthreads();
        sh[t] += v;
        __syncthreads();
    }
    g_noff[i + 1] = sh[t];
    if (t == 1023) g_nbsum[blockIdx.x] = sh[1023];
}
__global__ void k_nscan2() {
    __shared__ int sh[32];
    int t = threadIdx.x;
    int v = g_nbsum[t];
    sh[t] = v;
    __syncthreads();
    for (int ofs = 1; ofs < 32; ofs <<= 1) {
        int w = (t >= ofs) ? sh[t - ofs] : 0;
        __syncthreads();
        sh[t] += w;
        __syncthreads();
    }
    g_nbofs[t] = sh[t] - v;
}
__global__ void k_scan3_all() {
    int i = blockIdx.x * 1024 + threadIdx.x;
    int inc = g_off[i + 1] + g_bofs[i >> 10];
    g_off[i + 1] = inc;
    g_cur[i] = inc - g_deg[i];
    if (i < NGn) {
        int ninc = g_noff[i + 1] + g_nbofs[i >> 10];
        g_noff[i + 1] = ninc;
        g_ncur[i] = ninc - g_ndeg[i];
    }
    if (i == 0) { g_off[0] = 0; g_noff[0] = 0; }
}
__global__ void k_fill_all(const int* __restrict__ eilg, const int* __restrict__ eig) {
    int e = blockIdx.x * blockDim.x + threadIdx.x;
    if (e < ELGn) {
        int d = eilg[ELGn + e];
        int p = atomicAdd(&g_cur[d], 1);
        g_csr_src[p] = eilg[e];
        g_csr_eid[p] = e;
    }
    if (e < EGn) {
        int d = eig[EGn + e];
        int p = atomicAdd(&g_ncur[d], 1);
        g_ncsr[p] = e;
    }
}

// ---------------- genconv aggregation: g_y = act(x)[seg] + softmax-agg ----------------
// warp-per-segment, float4/lane; deg-2 batched loads (MLP ~7) + early self-row load
#define SLOT_BODY(xs, bs, at)                                                     \
    do {                                                                          \
        float4 _x = (xs);                                                         \
        if (doAct) {                                                              \
            _x.x = fmaxf(_x.x * gg.x + bb.x, 0.f);                                \
            _x.y = fmaxf(_x.y * gg.y + bb.y, 0.f);                                \
            _x.z = fmaxf(_x.z * gg.z + bb.z, 0.f);                                \
            _x.w = fmaxf(_x.w * gg.w + bb.w, 0.f);                                \
        }                                                                         \
        float4 _nb = bnb + (bs).x * wnb0 + (bs).y * wnb1 + (bs).z * wnb2 + (bs).w * wnb3; \
        float4 _eb = beb + (at).x * web0 + (at).y * web1 + (at).z * web2 + (at).w * web3; \
        float4 _m;                                                                \
        _m.x = fmaxf(_x.x * _nb.x * _eb.x, 0.f) + EPSM;                           \
        _m.y = fmaxf(_x.y * _nb.y * _eb.y, 0.f) + EPSM;                           \
        _m.z = fmaxf(_x.z * _nb.z * _eb.z, 0.f) + EPSM;                           \
        _m.w = fmaxf(_x.w * _nb.w * _eb.w, 0.f) + EPSM;                           \
        float4 _ex;                                                               \
        _ex.x = __expf(fminf(_m.x * t, 60.f));                                    \
        _ex.y = __expf(fminf(_m.y * t, 60.f));                                    \
        _ex.z = __expf(fminf(_m.z * t, 60.f));                                    \
        _ex.w = __expf(fminf(_m.w * t, 60.f));                                    \
        den += _ex;                                                               \
        num.x += _ex.x * _m.x;                                                    \
        num.y += _ex.y * _m.y;                                                    \
        num.z += _ex.z * _m.z;                                                    \
        num.w += _ex.w * _m.w;                                                    \
    } while (0)

__global__ __launch_bounds__(128) void k_genconv(
    const float* __restrict__ W_nb, const float* __restrict__ b_nb,
    const float* __restrict__ W_eb, const float* __restrict__ b_eb,
    const float* __restrict__ basis, const float* __restrict__ attr,
    const float* __restrict__ tvals, int layer,
    const float* __restrict__ gamma, const float* __restrict__ beta) {
    const int lane = threadIdx.x & 31;
    const int f = lane * 4;
    const int gw = (blockIdx.x * blockDim.x + threadIdx.x) >> 5;
    const int nw = (gridDim.x * blockDim.x) >> 5;
    const int doAct = layer > 0;

    float4 wnb0 = *(const float4*)&W_nb[0 * Hn + f];
    float4 wnb1 = *(const float4*)&W_nb[1 * Hn + f];
    float4 wnb2 = *(const float4*)&W_nb[2 * Hn + f];
    float4 wnb3 = *(const float4*)&W_nb[3 * Hn + f];
    float4 web0 = *(const float4*)&W_eb[0 * Hn + f];
    float4 web1 = *(const float4*)&W_eb[1 * Hn + f];
    float4 web2 = *(const float4*)&W_eb[2 * Hn + f];
    float4 web3 = *(const float4*)&W_eb[3 * Hn + f];
    float4 bnb = *(const float4*)&b_nb[f];
    float4 beb = *(const float4*)&b_eb[f];
    const float t = tvals[layer];
    float4 gg = f4zero(), bb = f4zero();
    if (doAct) {
        gg = BNINV * (*(const float4*)&gamma[(layer - 1) * Hn + f]);
        bb = *(const float4*)&beta[(layer - 1) * Hn + f];
    }

    for (int sg = gw; sg < EGn; sg += nw) {
        int o0 = g_off[sg], o1 = g_off[sg + 1];
        // issue self row early — overlaps with slot chain
        float4 self = *(const float4*)&g_h[(size_t)sg * Hn + f];
        float4 num = f4zero(), den = f4zero();
        int o = o0;
        // batched pairs: all 6 loads issued before dependent math
        for (; o + 2 <= o1; o += 2) {
            int sv0 = g_csr_src[o], sv1 = g_csr_src[o + 1];
            int e0 = g_csr_eid[o], e1 = g_csr_eid[o + 1];
            float4 x0 = *(const float4*)&g_h[(size_t)sv0 * Hn + f];
            float4 x1 = *(const float4*)&g_h[(size_t)sv1 * Hn + f];
            float4 bs0 = *(const float4*)&basis[sv0 * 4];
            float4 bs1 = *(const float4*)&basis[sv1 * 4];
            float4 at0 = *(const float4*)&attr[e0 * 4];
            float4 at1 = *(const float4*)&attr[e1 * 4];
            SLOT_BODY(x0, bs0, at0);
            SLOT_BODY(x1, bs1, at1);
        }
        if (o < o1) {
            int sv0 = g_csr_src[o];
            int e0 = g_csr_eid[o];
            float4 x0 = *(const float4*)&g_h[(size_t)sv0 * Hn + f];
            float4 bs0 = *(const float4*)&basis[sv0 * 4];
            float4 at0 = *(const float4*)&attr[e0 * 4];
            SLOT_BODY(x0, bs0, at0);
        }
        float4 outv = self;
        if (doAct) {
            outv.x = fmaxf(outv.x * gg.x + bb.x, 0.f);
            outv.y = fmaxf(outv.y * gg.y + bb.y, 0.f);
            outv.z = fmaxf(outv.z * gg.z + bb.z, 0.f);
            outv.w = fmaxf(outv.w * gg.w + bb.w, 0.f);
        }
        if (o1 > o0) {
            outv.x += num.x / den.x;
            outv.y += num.y / den.y;
            outv.z += num.z / den.z;
            outv.w += num.w / den.w;
        }
        *(float4*)&g_y[(size_t)sg * Hn + f] = outv;
    }
}

// ---------------- mma.sync update GEMM: g_h = g_y @ W[l] + b (+ g_h) — R8 proven ----------------
#define PADK  136
#define ROWB  (PADK * 2)          // 272 bytes per row
#define ABUF  (128 * ROWB)        // 34816 bytes per tile
#define GEMM_SMEM (4 * ABUF)      // 139264

__device__ __forceinline__ void cvt8(const float* v, uint4& hi, uint4& lo) {
    uint32_t hs[8], ls[8];
#pragma unroll
    for (int j = 0; j < 8; j++) {
        __nv_bfloat16 h = __float2bfloat16_rn(v[j]);
        float r = v[j] - __bfloat162float(h);
        hs[j] = (uint32_t)__bfloat16_as_ushort(h);
        ls[j] = (uint32_t)__bfloat16_as_ushort(__float2bfloat16_rn(r));
    }
    hi.x = hs[0] | (hs[1] << 16); hi.y = hs[2] | (hs[3] << 16);
    hi.z = hs[4] | (hs[5] << 16); hi.w = hs[6] | (hs[7] << 16);
    lo.x = ls[0] | (ls[1] << 16); lo.y = ls[2] | (ls[3] << 16);
    lo.z = ls[4] | (ls[5] << 16); lo.w = ls[6] | (ls[7] << 16);
}

__global__ __launch_bounds__(256) void k_gemm_mma(const float* __restrict__ bias,
                                                  int layer, int addRes) {
    extern __shared__ char smem[];
    const uint32_t sb = smem_u32(smem);
    const int tid = threadIdx.x;
    const int wid = tid >> 5;
    const int lane = tid & 31;
    const int row0 = blockIdx.x * 128;
    const uint32_t OF_AH = 0, OF_AL = ABUF, OF_BH = 2 * ABUF, OF_BL = 3 * ABUF;

    const float* src = g_y + (size_t)row0 * Hn;
#pragma unroll
    for (int i = 0; i < 8; i++) {
        int u = tid + i * 256;
        int r = u >> 4, cb = u & 15;
        float v[8];
        *(float4*)&v[0] = *(const float4*)(src + r * Hn + cb * 8);
        *(float4*)&v[4] = *(const float4*)(src + r * Hn + cb * 8 + 4);
        uint4 hi, lo;
        cvt8(v, hi, lo);
        *(uint4*)(smem + OF_AH + r * ROWB + cb * 16) = hi;
        *(uint4*)(smem + OF_AL + r * ROWB + cb * 16) = lo;
    }
    {
        const uint4* WH = (const uint4*)(g_WtH + layer * Hn * Hn);
        const uint4* WL = (const uint4*)(g_WtL + layer * Hn * Hn);
#pragma unroll
        for (int i = 0; i < 8; i++) {
            int u = tid + i * 256;
            int r = u >> 4, cb = u & 15;
            *(uint4*)(smem + OF_BH + r * ROWB + cb * 16) = WH[u];
            *(uint4*)(smem + OF_BL + r * ROWB + cb * 16) = WL[u];
        }
    }
    __syncthreads();

    const int wm = wid >> 1;
    const int wn = wid & 1;
    const int rA = wm * 32;
    const int nBase = wn * 64;

    float acc[2][8][4];
#pragma unroll
    for (int a = 0; a < 2; a++)
#pragma unroll
        for (int b = 0; b < 8; b++)
#pragma unroll
            for (int c = 0; c < 4; c++) acc[a][b][c] = 0.f;

    const int a_row = lane & 15;
    const int a_kof = (lane >> 4) * 8;
    const int b_row = ((lane >> 4) << 3) + (lane & 7);
    const int b_kof = ((lane >> 3) & 1) * 8;

#pragma unroll
    for (int ks = 0; ks < 8; ks++) {
        const int k0 = ks * 16;
        uint32_t aH[2][4], aL[2][4], bH[4][4], bL[4][4];
#pragma unroll
        for (int mt = 0; mt < 2; mt++) {
            uint32_t ad = sb + OF_AH + (uint32_t)((rA + mt * 16 + a_row) * ROWB + (k0 + a_kof) * 2);
            ldsm_x4(aH[mt], ad);
            ldsm_x4(aL[mt], ad + ABUF);
        }
#pragma unroll
        for (int np = 0; np < 4; np++) {
            uint32_t bd = sb + OF_BH + (uint32_t)((nBase + np * 16 + b_row) * ROWB + (k0 + b_kof) * 2);
            ldsm_x4(bH[np], bd);
            ldsm_x4(bL[np], bd + ABUF);
        }
#pragma unroll
        for (int mt = 0; mt < 2; mt++)
#pragma unroll
            for (int np = 0; np < 4; np++) {
                mma_bf16(acc[mt][2 * np],     aH[mt], &bH[np][0]);
                mma_bf16(acc[mt][2 * np + 1], aH[mt], &bH[np][2]);
                mma_bf16(acc[mt][2 * np],     aL[mt], &bH[np][0]);
                mma_bf16(acc[mt][2 * np + 1], aL[mt], &bH[np][2]);
                mma_bf16(acc[mt][2 * np],     aH[mt], &bL[np][0]);
                mma_bf16(acc[mt][2 * np + 1], aH[mt], &bL[np][2]);
            }
    }

    const int tg = lane >> 2, tig = lane & 3;
#pragma unroll
    for (int mt = 0; mt < 2; mt++)
#pragma unroll
        for (int nt = 0; nt < 8; nt++) {
            int col = nBase + nt * 8 + tig * 2;
            float2 bv = *(const float2*)&bias[col];
            int r1 = row0 + rA + mt * 16 + tg;
            int r2 = r1 + 8;
            float2 o1 = make_float2(acc[mt][nt][0] + bv.x, acc[mt][nt][1] + bv.y);
            float2 o2 = make_float2(acc[mt][nt][2] + bv.x, acc[mt][nt][3] + bv.y);
            if (addRes) {
                float2 q1 = *(const float2*)&g_h[(size_t)r1 * Hn + col];
                float2 q2 = *(const float2*)&g_h[(size_t)r2 * Hn + col];
                o1.x += q1.x; o1.y += q1.y;
                o2.x += q2.x; o2.y += q2.y;
            }
            *(float2*)&g_h[(size_t)r1 * Hn + col] = o1;
            *(float2*)&g_h[(size_t)r2 * Hn + col] = o2;
        }
}

// ---------------- final BN + node gather ----------------
__global__ __launch_bounds__(256) void k_nemb(const float* __restrict__ gamma,
                                              const float* __restrict__ beta) {
    const int lane = threadIdx.x & 31;
    const int wid = threadIdx.x >> 5;
    const int f = lane * 4;
    const int n = blockIdx.x * 8 + wid;

    float4 gs, bt;
    gs.x = gamma[(Ln - 1) * Hn + f + 0] * BNINV;
    gs.y = gamma[(Ln - 1) * Hn + f + 1] * BNINV;
    gs.z = gamma[(Ln - 1) * Hn + f + 2] * BNINV;
    gs.w = gamma[(Ln - 1) * Hn + f + 3] * BNINV;
    bt = *(const float4*)&beta[(Ln - 1) * Hn + f];

    int o0 = g_noff[n], o1 = g_noff[n + 1];
    float4 acc = f4zero();
    int o = o0;
    for (; o + 2 <= o1; o += 2) {
        int e0 = g_ncsr[o], e1 = g_ncsr[o + 1];
        float4 v0 = *(const float4*)&g_h[(size_t)e0 * Hn + f];
        float4 v1 = *(const float4*)&g_h[(size_t)e1 * Hn + f];
        acc += v0;
        acc += v1;
    }
    if (o < o1) {
        int e0 = g_ncsr[o];
        acc += *(const float4*)&g_h[(size_t)e0 * Hn + f];
    }
    float deg = (float)(o1 - o0);
    float4 outv;
    outv.x = gs.x * acc.x + deg * bt.x;
    outv.y = gs.y * acc.y + deg * bt.y;
    outv.z = gs.z * acc.z + deg * bt.z;
    outv.w = gs.w * acc.w + deg * bt.w;
    *(float4*)&g_nemb[(size_t)n * Hn + f] = outv;
}

// ---------------- pooling + prediction head ----------------
__global__ __launch_bounds__(128) void k_pool_pred(const int* __restrict__ batch,
                                                   const float* __restrict__ W_pred,
                                                   const float* __restrict__ b_pred,
                                                   float* __restrict__ out) {
    int b = blockIdx.x;
    int f = threadIdx.x;
    int lo = 0, hi = NGn;
    while (lo < hi) { int mid = (lo + hi) >> 1; if (batch[mid] < b) lo = mid + 1; else hi = mid; }
    int start = lo;
    hi = NGn;
    while (lo < hi) { int mid = (lo + hi) >> 1; if (batch[mid] < b + 1) lo = mid + 1; else hi = mid; }
    int end = lo;
    float acc = 0.f;
    for (int n = start; n < end; n++) acc += g_nemb[n * Hn + f];
    __shared__ float mean[Hn];
    mean[f] = acc / fmaxf((float)(end - start), 1.0f);
    __syncthreads();
    if (f < TKn) {
        float o = b_pred[f];
        for (int k = 0; k < Hn; k++) o += mean[k] * W_pred[k * TKn + f];
        out[b * TKn + f] = o;
    }
}

// ---------------- launch ----------------
extern "C" void kernel_launch(void* const* d_in, const int* in_sizes, int n_in,
                              void* d_out, int out_size) {
    const float* x_g      = (const float*)d_in[0];
    const float* ea_g     = (const float*)d_in[1];
    const float* x_lg     = (const float*)d_in[2];
    const float* basis    = (const float*)d_in[3];
    const float* attr_lg  = (const float*)d_in[4];
    const int*   eig      = (const int*)d_in[5];
    const int*   eilg     = (const int*)d_in[6];
    const int*   batch    = (const int*)d_in[7];
    const float* W_enc    = (const float*)d_in[8];
    const float* b_enc    = (const float*)d_in[9];
    const float* W_msg    = (const float*)d_in[10];
    const float* b_msg    = (const float*)d_in[11];
    const float* W_nb     = (const float*)d_in[12];
    const float* b_nb     = (const float*)d_in[13];
    const float* W_eb     = (const float*)d_in[14];
    const float* b_eb     = (const float*)d_in[15];
    const float* W_gcn    = (const float*)d_in[16];
    const float* b_gcn    = (const float*)d_in[17];
    const float* t_vals   = (const float*)d_in[18];
    const float* gamma    = (const float*)d_in[19];
    const float* beta     = (const float*)d_in[20];
    const float* W_pred   = (const float*)d_in[21];
    const float* b_pred   = (const float*)d_in[22];
    float* out = (float*)d_out;

    cudaFuncSetAttribute(k_gemm_mma, cudaFuncAttributeMaxDynamicSharedMemorySize, GEMM_SMEM);

    // prep
    k_params<<<65, 128>>>(W_enc, W_msg, b_enc, b_msg);
    k_wt<<<(Ln * Hn * Hn) / 256, 256>>>(W_gcn);
    k_u<<<NGn / 32, 128>>>(x_g);
    k_msg<<<EGn / 64, 256>>>(W_msg, ea_g, x_lg, eig);

    // both CSRs (merged kernels)
    k_zero_all<<<EGn / 256, 256>>>();
    k_hist_all<<<ELGn / 256, 256>>>(eilg, eig);
    k_scan1<<<128, 1024>>>();
    k_scan2<<<1, 128>>>();
    k_nscan1<<<32, 1024>>>();
    k_nscan2<<<1, 32>>>();
    k_scan3_all<<<128, 1024>>>();
    k_fill_all<<<ELGn / 256, 256>>>(eilg, eig);

    // 4 GENConv layers (res+ for l>0): genconv (g_h -> g_y), gemm (g_y -> g_h)
    for (int l = 0; l < Ln; l++) {
        k_genconv<<<4096, 128>>>(W_nb, b_nb, W_eb, b_eb, basis, attr_lg,
                                 t_vals, l, gamma, beta);
        k_gemm_mma<<<EGn / 128, 256, GEMM_SMEM>>>(b_gcn + l * Hn, l, l > 0 ? 1 : 0);
    }

    // final BN + gather to graph nodes, pool per batch (sorted), predict
    k_nemb<<<NGn / 8, 256>>>(gamma, beta);
    k_pool_pred<<<Bn, 128>>>(batch, W_pred, b_pred, out);
}